// round 3
// baseline (speedup 1.0000x reference)
#include <cuda_runtime.h>
#include <cuda_bf16.h>

// Problem constants (fixed by the reference):
//   B=8, C=16, H=512, W=512, M=N=15  -> P=Q=16, BC=128
//   basis: [H*W, 16, 16] float32 (separable Bernstein tensor products)
//   K:     [B*C, 16, 16] float32
//   out:   [B*C, H, W]   float32
#define Hh 512
#define Ww 512
#define BC 128
#define Pp 16
#define Qq 16
#define HT 64   // h-rows per block in stage 3

// Scratch (static __device__ arrays; no runtime allocation).
__device__ float g_Bu[Hh * Pp];          //  32 KB
__device__ float g_Bv[Ww * Qq];          //  32 KB
__device__ float g_T[BC * Pp * Ww];      //   4 MB

// -------------------------------------------------------------------------
// Stage 1: recover separable factors from the basis tensor.
// basis[h*W + w, p, q] = Bu[h,p] * Bv[w,q], with Bernstein partition of
// unity: sum_p Bu[h,p] == 1 and sum_q Bv[w,q] == 1 for every h, w. Hence:
//   Bu[h,p] = sum_q basis[(h*W + 0), p, q]
//   Bv[w,q] = sum_p basis[(0*W + w), p, q]
// -------------------------------------------------------------------------
__global__ void bez_extract_kernel(const float* __restrict__ basis) {
    int idx = blockIdx.x * blockDim.x + threadIdx.x;
    if (idx < Hh * Pp) {
        int h = idx / Pp;
        int p = idx % Pp;
        const float* row = basis + (size_t)h * Ww * 256 + p * 16;
        float s = 0.f;
#pragma unroll
        for (int q = 0; q < 16; ++q) s += row[q];
        g_Bu[h * Pp + p] = s;
    } else if (idx < Hh * Pp + Ww * Qq) {
        int j = idx - Hh * Pp;
        int w = j / Qq;
        int q = j % Qq;
        const float* row = basis + (size_t)w * 256 + q;
        float s = 0.f;
#pragma unroll
        for (int p = 0; p < 16; ++p) s += row[p * 16];
        g_Bv[w * Qq + q] = s;
    }
}

// -------------------------------------------------------------------------
// Stage 2: T[bc, p, w] = sum_q Bv[w,q] * K[bc, p, q]
// One block per bc; K[bc] (1 KB) staged in smem.
// -------------------------------------------------------------------------
__global__ void bez_stage2_kernel(const float* __restrict__ Kmat) {
    __shared__ float sK[Pp * Qq];
    const int bc  = blockIdx.x;
    const int tid = threadIdx.x;          // blockDim.x == 256
    sK[tid] = Kmat[bc * 256 + tid];
    __syncthreads();

    for (int w = tid; w < Ww; w += 256) {
        float bv[Qq];
#pragma unroll
        for (int q = 0; q < Qq; ++q) bv[q] = g_Bv[w * Qq + q];
#pragma unroll
        for (int p = 0; p < Pp; ++p) {
            float s = 0.f;
#pragma unroll
            for (int q = 0; q < Qq; ++q) s += bv[q] * sK[p * Qq + q];
            g_T[((size_t)bc * Pp + p) * Ww + w] = s;
        }
    }
}

// -------------------------------------------------------------------------
// Stage 3: out[bc, h, w] = sum_p Bu[h,p] * T[bc, p, w]
// Grid: (H/HT, BC). Block: 128 threads; thread t owns the float4 column
// w = 4*t. T[bc,p,4t..4t+3] lives in 16 float4 registers for the whole
// block lifetime; Bu tile broadcast from smem. 64 FFMA per float4 store;
// store bandwidth should be the binding resource.
// -------------------------------------------------------------------------
__global__ __launch_bounds__(128) void bez_stage3_kernel(float* __restrict__ out) {
    const int bc  = blockIdx.y;
    const int h0  = blockIdx.x * HT;
    const int tid = threadIdx.x;          // 0..127 -> float4 column index

    __shared__ float sBu[HT * Pp];        // 4 KB

    // Kick off the 16 float4 global loads first (MLP), then fill smem.
    float4 t[Pp];
    const float4* __restrict__ Tp =
        reinterpret_cast<const float4*>(g_T + (size_t)bc * Pp * Ww);
#pragma unroll
    for (int p = 0; p < Pp; ++p) t[p] = Tp[p * (Ww / 4) + tid];

    for (int i = tid; i < HT * Pp; i += 128) sBu[i] = g_Bu[h0 * Pp + i];
    __syncthreads();

    float4* __restrict__ o =
        reinterpret_cast<float4*>(out + ((size_t)bc * Hh + h0) * Ww);
#pragma unroll 4
    for (int hh = 0; hh < HT; ++hh) {
        float4 acc = make_float4(0.f, 0.f, 0.f, 0.f);
#pragma unroll
        for (int p = 0; p < Pp; ++p) {
            const float b = sBu[hh * Pp + p];
            acc.x += b * t[p].x;
            acc.y += b * t[p].y;
            acc.z += b * t[p].z;
            acc.w += b * t[p].w;
        }
        o[hh * (Ww / 4) + tid] = acc;
    }
}

// -------------------------------------------------------------------------
// Launch: identify K vs basis by element count (K = 32768, basis = 67108864).
// Three ordered launches on the capture stream.
// -------------------------------------------------------------------------
extern "C" void kernel_launch(void* const* d_in, const int* in_sizes, int n_in,
                              void* d_out, int out_size) {
    const float* Kmat  = nullptr;
    const float* basis = nullptr;
    for (int i = 0; i < n_in; ++i) {
        if (in_sizes[i] == BC * Pp * Qq)            Kmat  = (const float*)d_in[i];
        else if (in_sizes[i] == Hh * Ww * Pp * Qq)  basis = (const float*)d_in[i];
    }
    float* out = (float*)d_out;

    // Stage 1: 16384 factor entries (reads only ~1 MB of basis).
    bez_extract_kernel<<<(Hh * Pp + Ww * Qq + 255) / 256, 256>>>(basis);
    // Stage 2: per-bc transform into g_T (4 MB).
    bez_stage2_kernel<<<BC, 256>>>(Kmat);
    // Stage 3: main output kernel (134 MB store-bound).
    dim3 grid3(Hh / HT, BC);
    bez_stage3_kernel<<<grid3, 128>>>(out);
}

// round 5
// speedup vs baseline: 1.0463x; 1.0463x over previous
#include <cuda_runtime.h>
#include <cuda_bf16.h>

// B=8, C=16, H=512, W=512, M=N=15 -> P=Q=16, BC=128
// basis: [H*W,16,16] f32 (separable Bernstein products), K: [128,16,16] f32
// out: [128,512,512] f32
#define Hh 512
#define Ww 512
#define BC 128
#define Pp 16
#define Qq 16
#define HT 64

__device__ float g_Bu[Hh * Pp];       // 32 KB
__device__ float g_Bv[Ww * Qq];       // 32 KB
__device__ float g_T[BC * Pp * Ww];   //  4 MB

// ---- f32x2 packed helpers (Blackwell) ------------------------------------
__device__ __forceinline__ unsigned long long pack_f32x2(float x, float y) {
    unsigned long long r;
    asm("mov.b64 %0, {%1, %2};" : "=l"(r) : "f"(x), "f"(y));
    return r;
}
__device__ __forceinline__ void unpack_f32x2(unsigned long long v, float& x, float& y) {
    asm("mov.b64 {%0, %1}, %2;" : "=f"(x), "=f"(y) : "l"(v));
}
__device__ __forceinline__ unsigned long long fma_f32x2(
    unsigned long long a, unsigned long long b, unsigned long long c) {
    unsigned long long d;
    asm("fma.rn.f32x2 %0, %1, %2, %3;" : "=l"(d) : "l"(a), "l"(b), "l"(c));
    return d;
}

// -------------------------------------------------------------------------
// Stage 1: recover separable factors (Bernstein partition of unity):
//   Bu[h,p] = sum_q basis[h*W + 0, p, q]
//   Bv[w,q] = sum_p basis[0*W + w, p, q]
// -------------------------------------------------------------------------
__global__ void bez_extract_kernel(const float* __restrict__ basis) {
    int idx = blockIdx.x * blockDim.x + threadIdx.x;
    if (idx < Hh * Pp) {
        int h = idx >> 4;
        int p = idx & 15;
        const float4* r =
            reinterpret_cast<const float4*>(basis + (size_t)h * Ww * 256 + p * 16);
        float4 a = r[0], b = r[1], c = r[2], d = r[3];
        g_Bu[idx] = ((a.x + a.y) + (a.z + a.w)) + ((b.x + b.y) + (b.z + b.w)) +
                    ((c.x + c.y) + (c.z + c.w)) + ((d.x + d.y) + (d.z + d.w));
    } else if (idx < Hh * Pp + Ww * Qq) {
        int j = idx - Hh * Pp;
        int w = j >> 4;
        int q = j & 15;
        const float* row = basis + (size_t)w * 256 + q;
        float s = 0.f;
#pragma unroll
        for (int p = 0; p < 16; ++p) s += row[p * 16];
        g_Bv[j] = s;
    }
}

// -------------------------------------------------------------------------
// Stage 2: T[bc, p, w] = sum_q Bv[w,q] * K[bc, p, q]
// -------------------------------------------------------------------------
__global__ void bez_stage2_kernel(const float* __restrict__ Kmat) {
    __shared__ float sK[Pp * Qq];
    const int bc  = blockIdx.x;
    const int tid = threadIdx.x;          // 256
    sK[tid] = Kmat[bc * 256 + tid];
    __syncthreads();

    for (int w = tid; w < Ww; w += 256) {
        float bv[Qq];
#pragma unroll
        for (int q = 0; q < Qq; ++q) bv[q] = g_Bv[w * Qq + q];
#pragma unroll
        for (int p = 0; p < Pp; ++p) {
            float s = 0.f;
#pragma unroll
            for (int q = 0; q < Qq; ++q) s += bv[q] * sK[p * Qq + q];
            g_T[((size_t)bc * Pp + p) * Ww + w] = s;
        }
    }
}

// -------------------------------------------------------------------------
// Stage 3: out[bc, h, w] = sum_p Bu[h,p] * T[bc, p, w]
// Thread t owns float4 column w=4t as two packed f32x2 lanes; T column
// register-resident; Bu splatted into smem as duplicated 64-bit words.
// 32 fma.rn.f32x2 per float4 store -> store-bandwidth bound.
// -------------------------------------------------------------------------
__global__ __launch_bounds__(128) void bez_stage3_kernel(float* __restrict__ out) {
    const int bc  = blockIdx.y;
    const int h0  = blockIdx.x * HT;
    const int tid = threadIdx.x;          // 0..127

    __shared__ unsigned long long sBu2[HT * Pp];   // 8 KB, value duplicated lo/hi

    unsigned long long tlo[Pp], thi[Pp];
    const float4* __restrict__ Tp =
        reinterpret_cast<const float4*>(g_T + (size_t)bc * Pp * Ww);
#pragma unroll
    for (int p = 0; p < Pp; ++p) {
        float4 v = Tp[p * (Ww / 4) + tid];
        tlo[p] = pack_f32x2(v.x, v.y);
        thi[p] = pack_f32x2(v.z, v.w);
    }
    for (int i = tid; i < HT * Pp; i += 128) {
        unsigned int b = __float_as_uint(g_Bu[h0 * Pp + i]);
        sBu2[i] = ((unsigned long long)b << 32) | b;
    }
    __syncthreads();

    float4* __restrict__ o =
        reinterpret_cast<float4*>(out + ((size_t)bc * Hh + h0) * Ww);
#pragma unroll 2
    for (int hh = 0; hh < HT; ++hh) {
        unsigned long long alo = 0ull, ahi = 0ull;   // two +0.0f each
#pragma unroll
        for (int p = 0; p < Pp; ++p) {
            const unsigned long long b = sBu2[hh * Pp + p];
            alo = fma_f32x2(b, tlo[p], alo);
            ahi = fma_f32x2(b, thi[p], ahi);
        }
        float4 r;
        unpack_f32x2(alo, r.x, r.y);
        unpack_f32x2(ahi, r.z, r.w);
        __stcs(&o[hh * (Ww / 4) + tid], r);
    }
}

// -------------------------------------------------------------------------
extern "C" void kernel_launch(void* const* d_in, const int* in_sizes, int n_in,
                              void* d_out, int out_size) {
    const float* Kmat  = nullptr;
    const float* basis = nullptr;
    for (int i = 0; i < n_in; ++i) {
        if (in_sizes[i] == BC * Pp * Qq)            Kmat  = (const float*)d_in[i];
        else if (in_sizes[i] == Hh * Ww * Pp * Qq)  basis = (const float*)d_in[i];
    }
    float* out = (float*)d_out;

    bez_extract_kernel<<<(Hh * Pp + Ww * Qq + 255) / 256, 256>>>(basis);
    bez_stage2_kernel<<<BC, 256>>>(Kmat);
    dim3 grid3(Hh / HT, BC);
    bez_stage3_kernel<<<grid3, 128>>>(out);
}